// round 1
// baseline (speedup 1.0000x reference)
#include <cuda_runtime.h>

// NAIS concat-attention scoring:
//   qp[b,h,d]    = bias[h,d] + sum_e Q[b,h,e] * W_c[h, e, d]          (e < 64)
//   hid[b,h,k,d] = relu( qp[b,h,d] + sum_e K[b,h,k,e] * W_c[h, 64+e, d] )
//   out[b,h,k]   = sum_d hid[b,h,k,d] * W_o[h,d]
//
// Structure: per-(b,h) GEMM [8192 x 64] @ [64 x 64] with fused relu-dot epilogue.

namespace {
constexpr int Bc = 32;
constexpr int Hc = 8;
constexpr int KL = 8192;
constexpr int Dd = 64;

constexpr int TILE_M   = 128;   // k-rows per smem tile
constexpr int KCHUNK   = 512;   // k-rows per block (4 tiles)
constexpr int NTHREADS = 256;
constexpr int ASTRIDE  = 132;   // padded row-stride (floats) of transposed A tile
                                // (multiple of 4 -> 16B-aligned float4 rows)

constexpr int SMEM_FLOATS = Dd * ASTRIDE   // As: K tile transposed [e][row]
                          + Dd * Dd        // Bs: Wk [e][d]
                          + Dd             // qp
                          + Dd;            // wo
constexpr int SMEM_BYTES = SMEM_FLOATS * 4; // 50688 B
}

__global__ void __launch_bounds__(NTHREADS, 3)
nais_score_kernel(const float* __restrict__ Q,
                  const float* __restrict__ K,
                  const float* __restrict__ Wc,
                  const float* __restrict__ Wo,
                  const float* __restrict__ bias,
                  float* __restrict__ out)
{
    extern __shared__ float smem[];
    float* As = smem;                       // [Dd][ASTRIDE]  (e-major, row minor)
    float* Bs = smem + Dd * ASTRIDE;        // [Dd][Dd]       (e-major, d minor)
    float* qp = Bs + Dd * Dd;               // [Dd]
    float* wo = qp + Dd;                    // [Dd]

    const int tid   = threadIdx.x;
    const int bid   = blockIdx.x;
    const int bh    = bid >> 4;             // (b*H + h)
    const int chunk = bid & 15;             // which 512-row chunk of KLEN
    const int h     = bh & (Hc - 1);

    const float* __restrict__ WcH   = Wc + (size_t)h * 2 * Dd * Dd;
    const float* __restrict__ Kbase = K + (size_t)bh * KL * Dd
                                        + (size_t)chunk * KCHUNK * Dd;
    float* __restrict__ outp = out + (size_t)bh * KL + (size_t)chunk * KCHUNK;

    // ---- prologue: Wk -> Bs, qp & wo -> smem ----
    #pragma unroll
    for (int i = 0; i < (Dd * Dd) / NTHREADS; i++) {
        int idx = tid + i * NTHREADS;       // idx = e*64 + d
        Bs[idx] = WcH[Dd * Dd + idx];       // bottom half of W_c = Wk
    }
    if (tid < Dd) {
        wo[tid] = Wo[h * Dd + tid];
        float acc = bias[h * Dd + tid];
        const float* __restrict__ q = Q + (size_t)bh * Dd;
        #pragma unroll 8
        for (int e = 0; e < Dd; e++)
            acc = fmaf(q[e], WcH[e * Dd + tid], acc);
        qp[tid] = acc;
    }
    __syncthreads();

    // thread tile mapping: 16 row-groups x 16 col-groups
    const int tr   = tid >> 4;              // 0..15 -> rows [tr*8, tr*8+8)
    const int tc   = tid & 15;              // 0..15 -> cols [tc*4, tc*4+4)
    const int row0 = tr * 8;
    const int col0 = tc * 4;

    float qpv[4], wov[4];
    #pragma unroll
    for (int j = 0; j < 4; j++) { qpv[j] = qp[col0 + j]; wov[j] = wo[col0 + j]; }

    for (int t = 0; t < KCHUNK / TILE_M; t++) {
        // ---- load K tile (128 x 64), store transposed As[e][row] ----
        #pragma unroll
        for (int i = 0; i < (TILE_M * Dd / 4) / NTHREADS; i++) {  // 8 float4s/thread
            int flat = tid + i * NTHREADS;   // 0..2047
            int row  = flat >> 4;            // 16 float4 per 64-float row
            int e4   = flat & 15;
            float4 g = reinterpret_cast<const float4*>(
                           Kbase + (size_t)(t * TILE_M + row) * Dd)[e4];
            As[(e4 * 4 + 0) * ASTRIDE + row] = g.x;
            As[(e4 * 4 + 1) * ASTRIDE + row] = g.y;
            As[(e4 * 4 + 2) * ASTRIDE + row] = g.z;
            As[(e4 * 4 + 3) * ASTRIDE + row] = g.w;
        }
        __syncthreads();

        // ---- register-tiled GEMM: acc[8][4] += A[row, e] * Wk[e, col] ----
        float acc[8][4];
        #pragma unroll
        for (int i = 0; i < 8; i++)
            #pragma unroll
            for (int j = 0; j < 4; j++) acc[i][j] = 0.f;

        #pragma unroll 8
        for (int e = 0; e < Dd; e++) {
            const float4 a0 = *reinterpret_cast<const float4*>(As + e * ASTRIDE + row0);
            const float4 a1 = *reinterpret_cast<const float4*>(As + e * ASTRIDE + row0 + 4);
            const float4 b  = *reinterpret_cast<const float4*>(Bs + e * Dd + col0);
            const float av[8] = {a0.x, a0.y, a0.z, a0.w, a1.x, a1.y, a1.z, a1.w};
            const float bv[4] = {b.x, b.y, b.z, b.w};
            #pragma unroll
            for (int i = 0; i < 8; i++)
                #pragma unroll
                for (int j = 0; j < 4; j++)
                    acc[i][j] = fmaf(av[i], bv[j], acc[i][j]);
        }

        // ---- fused epilogue: relu(acc + qp) . wo, reduce over the 16 tc lanes ----
        #pragma unroll
        for (int i = 0; i < 8; i++) {
            float p = 0.f;
            #pragma unroll
            for (int j = 0; j < 4; j++) {
                float v = acc[i][j] + qpv[j];
                p = fmaf(fmaxf(v, 0.f), wov[j], p);
            }
            p += __shfl_xor_sync(0xffffffffu, p, 1);
            p += __shfl_xor_sync(0xffffffffu, p, 2);
            p += __shfl_xor_sync(0xffffffffu, p, 4);
            p += __shfl_xor_sync(0xffffffffu, p, 8);
            if (tc == 0)
                outp[t * TILE_M + row0 + i] = p;
        }
        __syncthreads();   // protect As before next tile's transpose writes
    }
}

extern "C" void kernel_launch(void* const* d_in, const int* in_sizes, int n_in,
                              void* d_out, int out_size)
{
    const float* Q    = (const float*)d_in[0];
    const float* K    = (const float*)d_in[1];
    const float* Wc   = (const float*)d_in[2];
    const float* Wo   = (const float*)d_in[3];
    const float* bias = (const float*)d_in[4];
    float* out = (float*)d_out;

    cudaFuncSetAttribute(nais_score_kernel,
                         cudaFuncAttributeMaxDynamicSharedMemorySize, SMEM_BYTES);

    const int grid = Bc * Hc * (KL / KCHUNK);   // 4096 blocks
    nais_score_kernel<<<grid, NTHREADS, SMEM_BYTES>>>(Q, K, Wc, Wo, bias, out);
}

// round 4
// speedup vs baseline: 3.3414x; 3.3414x over previous
#include <cuda_runtime.h>
#include <cstdint>

// NAIS scoring via warp-level tf32 mma.sync (sm_80 PTX -> valid on plain sm_103 target;
// tcgen05 is rejected by this toolchain's non-'a' PTX target).
//
//   qp[d]  = bias[h,d] + sum_e Q[b,h,e] * Wc[h,e,d]            (fp32, exact)
//   out[k] = sum_d relu( qp[d] + (K[k,:] @ Wk)[d] ) * Wo[h,d]  (K@Wk in tf32)
//
// m16n8k8 fragment layouts (PTX / CUTLASS SM80_16x8x8_F32TF32TF32F32_TN),
// g = lane>>2, c = lane&3:
//   A: a0=(g, s0) a1=(g+8, s0) a2=(g, s1) a3=(g+8, s1)   (s0/s1 = k-slots c, c+4)
//   B: b0=(k s0, n=g) b1=(k s1, n=g)
//   C: c0=(g,2c) c1=(g,2c+1) c2=(g+8,2c) c3=(g+8,2c+1)
// k-slot -> physical column permutation (same for A and B, step s):
//   (c, slot0) -> 16c+2s, (c, slot1) -> 16c+2s+1   (bijective per step)

namespace {
constexpr int Bc = 32, Hc = 8, KL = 8192, Dd = 64;
constexpr int NTHREADS = 256;                 // 8 warps
constexpr int KCHUNK   = 2048;                // rows per block
constexpr int ROWS_PER_ITER = 256;            // 8 warps x 32 rows
constexpr int NITER    = KCHUNK / ROWS_PER_ITER;  // 8
}

__device__ __forceinline__ uint32_t f2tf(float f) {
    uint32_t r;
    asm("cvt.rna.tf32.f32 %0, %1;" : "=r"(r) : "f"(f));
    return r;
}

__device__ __forceinline__ void mma_tf32(float c[4],
                                         uint32_t a0, uint32_t a1, uint32_t a2, uint32_t a3,
                                         uint32_t b0, uint32_t b1) {
    asm volatile(
        "mma.sync.aligned.m16n8k8.row.col.f32.tf32.tf32.f32 "
        "{%0,%1,%2,%3}, {%4,%5,%6,%7}, {%8,%9}, {%0,%1,%2,%3};"
        : "+f"(c[0]), "+f"(c[1]), "+f"(c[2]), "+f"(c[3])
        : "r"(a0), "r"(a1), "r"(a2), "r"(a3), "r"(b0), "r"(b1));
}

__global__ void __launch_bounds__(NTHREADS, 2)
nais_mma_kernel(const float* __restrict__ Q, const float* __restrict__ K,
                const float* __restrict__ Wc, const float* __restrict__ Wo,
                const float* __restrict__ bias, float* __restrict__ out)
{
    // B fragments pre-packed: Bp[(nt*8 + s)*32 + lane] =
    //   { tf32 Wk[16c+2s][n], tf32 Wk[16c+2s+1][n] },  n = nt*8 + g
    __shared__ uint2 Bp[8 * 8 * 32];          // 16 KB
    __shared__ float qps[Dd], wos[Dd];

    const int tid  = threadIdx.x;
    const int w    = tid >> 5;
    const int lane = tid & 31;
    const int c    = lane & 3;                // threadID_in_group
    const int g    = lane >> 2;               // groupID

    const int bid   = blockIdx.x;
    const int bh    = bid >> 2;               // b*H + h
    const int chunk = bid & 3;
    const int h     = bh & (Hc - 1);

    const float* __restrict__ WcH = Wc + (size_t)h * 2 * Dd * Dd;
    const float* __restrict__ Wk  = WcH + Dd * Dd;    // bottom half: [e][d]
    const float* __restrict__ Kc  = K + (size_t)bh * KL * Dd + (size_t)chunk * KCHUNK * Dd;
    float* __restrict__ outp = out + (size_t)bh * KL + (size_t)chunk * KCHUNK;

    // ---- prologue ----
    #pragma unroll
    for (int i = 0; i < (8 * 8 * 32) / NTHREADS; i++) {   // 8 packs/thread
        int idx = tid + i * NTHREADS;          // ((nt*8 + s)*32 + ln)
        int ln = idx & 31, s = (idx >> 5) & 7, nt = idx >> 8;
        int cc = ln & 3, gg = ln >> 2;
        int e0 = 16 * cc + 2 * s;
        int n  = nt * 8 + gg;
        Bp[idx] = make_uint2(f2tf(Wk[e0 * Dd + n]), f2tf(Wk[(e0 + 1) * Dd + n]));
    }
    if (tid < Dd) {                            // qp = bias + Q @ Wq (fp32 exact); wo
        wos[tid] = Wo[h * Dd + tid];
        float acc = bias[h * Dd + tid];
        const float* __restrict__ q = Q + (size_t)bh * Dd;
        #pragma unroll 8
        for (int e = 0; e < Dd; e++) acc = fmaf(q[e], WcH[e * Dd + tid], acc);
        qps[tid] = acc;
    }
    __syncthreads();

    // ---- main loop: 32 rows per warp per iter, A straight from GMEM ----
    for (int it = 0; it < NITER; it++) {
        const int rowbase = it * ROWS_PER_ITER + w * 32;

        // A fragments: thread owns physical cols [16c, 16c+16) of rows rt*16 + hf*8 + g.
        // A[rt][hf][2s], A[rt][hf][2s+1] = k-slots 0/1 of step s.
        uint32_t A[2][2][16];
        #pragma unroll
        for (int rt = 0; rt < 2; rt++)
            #pragma unroll
            for (int hf = 0; hf < 2; hf++) {
                const int r = rowbase + rt * 16 + hf * 8 + g;
                const float4* p = reinterpret_cast<const float4*>(
                                      Kc + (size_t)r * Dd + 16 * c);
                float4 f0 = p[0], f1 = p[1], f2 = p[2], f3 = p[3];
                A[rt][hf][0]  = f2tf(f0.x); A[rt][hf][1]  = f2tf(f0.y);
                A[rt][hf][2]  = f2tf(f0.z); A[rt][hf][3]  = f2tf(f0.w);
                A[rt][hf][4]  = f2tf(f1.x); A[rt][hf][5]  = f2tf(f1.y);
                A[rt][hf][6]  = f2tf(f1.z); A[rt][hf][7]  = f2tf(f1.w);
                A[rt][hf][8]  = f2tf(f2.x); A[rt][hf][9]  = f2tf(f2.y);
                A[rt][hf][10] = f2tf(f2.z); A[rt][hf][11] = f2tf(f2.w);
                A[rt][hf][12] = f2tf(f3.x); A[rt][hf][13] = f2tf(f3.y);
                A[rt][hf][14] = f2tf(f3.z); A[rt][hf][15] = f2tf(f3.w);
            }

        float psum[2][2] = {{0.f, 0.f}, {0.f, 0.f}};

        #pragma unroll
        for (int nt = 0; nt < 8; nt++) {
            const float qp0 = qps[nt * 8 + 2 * c], qp1 = qps[nt * 8 + 2 * c + 1];
            const float w0  = wos[nt * 8 + 2 * c], w1  = wos[nt * 8 + 2 * c + 1];

            float acc0[4] = {0.f, 0.f, 0.f, 0.f};
            float acc1[4] = {0.f, 0.f, 0.f, 0.f};

            #pragma unroll
            for (int s = 0; s < 8; s++) {
                const uint2 b = Bp[(nt * 8 + s) * 32 + lane];
                // a0=(g,s0) a1=(g+8,s0) a2=(g,s1) a3=(g+8,s1)
                mma_tf32(acc0, A[0][0][2 * s], A[0][1][2 * s],
                               A[0][0][2 * s + 1], A[0][1][2 * s + 1], b.x, b.y);
                mma_tf32(acc1, A[1][0][2 * s], A[1][1][2 * s],
                               A[1][0][2 * s + 1], A[1][1][2 * s + 1], b.x, b.y);
            }
            // fused epilogue: C regs c0,c1 = row g cols (2c,2c+1); c2,c3 = row g+8
            psum[0][0] += fmaxf(acc0[0] + qp0, 0.f) * w0 + fmaxf(acc0[1] + qp1, 0.f) * w1;
            psum[0][1] += fmaxf(acc0[2] + qp0, 0.f) * w0 + fmaxf(acc0[3] + qp1, 0.f) * w1;
            psum[1][0] += fmaxf(acc1[0] + qp0, 0.f) * w0 + fmaxf(acc1[1] + qp1, 0.f) * w1;
            psum[1][1] += fmaxf(acc1[2] + qp0, 0.f) * w0 + fmaxf(acc1[3] + qp1, 0.f) * w1;
        }

        // reduce over the 4 lanes of each group (c = 0..3), then store
        #pragma unroll
        for (int rt = 0; rt < 2; rt++)
            #pragma unroll
            for (int hf = 0; hf < 2; hf++) {
                float p = psum[rt][hf];
                p += __shfl_xor_sync(0xffffffffu, p, 1);
                p += __shfl_xor_sync(0xffffffffu, p, 2);
                if (c == 0)
                    outp[rowbase + rt * 16 + hf * 8 + g] = p;
            }
    }
}

extern "C" void kernel_launch(void* const* d_in, const int* in_sizes, int n_in,
                              void* d_out, int out_size)
{
    const float* Q    = (const float*)d_in[0];
    const float* K    = (const float*)d_in[1];
    const float* Wc   = (const float*)d_in[2];
    const float* Wo   = (const float*)d_in[3];
    const float* bias = (const float*)d_in[4];
    float* out = (float*)d_out;

    const int grid = Bc * Hc * (KL / KCHUNK);   // 1024 blocks
    nais_mma_kernel<<<grid, NTHREADS>>>(Q, K, Wc, Wo, bias, out);
}